// round 1
// baseline (speedup 1.0000x reference)
#include <cuda_runtime.h>

constexpr int Wd = 1024, Hd = 1024;
constexpr long HW = (long)Wd * Hd;
constexpr int CIN = 18;

// ---------------------------------------------------------------------------
// Interior kernel: pixels x in [4,1020), y in [3,1021). No bounds checks.
// Each thread computes 4 consecutive x pixels (x0 % 4 == 0, aligned float4).
// Uses the expansion  sum_c rp*(fn-f)^2 = sum_c rp*fn^2 + sum_c(-2 rp f)*fn + K
// so the inner loop is 2 FFMA per (tap, channel) and fn^2 is shared across
// the 7 j-offsets and the 4 register-blocked pixels.
// ---------------------------------------------------------------------------
__global__ __launch_bounds__(256, 1)
void bilat_interior(const float* __restrict__ in, float* __restrict__ out)
{
    const int gxg = blockIdx.x * 32 + threadIdx.x;      // 0..255, use 0..253
    const int x0  = 4 + gxg * 4;
    const int y   = 3 + blockIdx.y * 8 + threadIdx.y;
    if (x0 > 1016 || y > 1020) return;
    const int b = blockIdx.z;

    const float* base = in + (long)b * CIN * HW;
    const long ctr = (long)y * Wd + x0;

    // Per-pixel params: rp = -(p^2), mf = -2*rp*f, K = sum rp*f^2
    float rp[8][4], mf[8][4], K[4] = {0.f, 0.f, 0.f, 0.f};
    #pragma unroll
    for (int c = 0; c < 8; ++c) {
        float4 fv = *(const float4*)(base + c * HW + ctr);
        float4 pv = *(const float4*)(base + (8 + c) * HW + ctr);
        const float f4[4] = {fv.x, fv.y, fv.z, fv.w};
        const float p4[4] = {pv.x, pv.y, pv.z, pv.w};
        #pragma unroll
        for (int p = 0; p < 4; ++p) {
            float r = -(p4[p] * p4[p]);
            rp[c][p] = r;
            mf[c][p] = -2.f * r * f4[p];
            K[p] = fmaf(r * f4[p], f4[p], K[p]);
        }
    }
    float sxl[4], syl[4];
    {
        float4 sv = *(const float4*)(base + 16 * HW + ctr);
        float4 tv = *(const float4*)(base + 17 * HW + ctr);
        const float s4[4] = {sv.x, sv.y, sv.z, sv.w};
        const float t4[4] = {tv.x, tv.y, tv.z, tv.w};
        #pragma unroll
        for (int p = 0; p < 4; ++p) {
            sxl[p] = -(s4[p] * s4[p]);
            syl[p] = -(t4[p] * t4[p]);
        }
    }

    float acc[3][4] = {}, ws[4] = {0.f, 0.f, 0.f, 0.f};

    #pragma unroll 1        // keep body ~13KB: inside I$ L1.5
    for (int i = 0; i < 7; ++i) {
        const int gy = y + i - 3;                        // always in [0,1023]
        const float* rowb = base + (long)gy * Wd + (x0 - 4);

        float s[7][4];
        #pragma unroll
        for (int j = 0; j < 7; ++j)
            #pragma unroll
            for (int p = 0; p < 4; ++p) s[j][p] = 0.f;

        float keep[3][12];   // neighbor rows of output channels 0..2

        // channel order 3,4,5,6,7,0,1,2 so kept rows are live only briefly
        #pragma unroll
        for (int cc = 0; cc < 8; ++cc) {
            const int c = (cc < 5) ? cc + 3 : cc - 5;
            const float* r0 = rowb + c * HW;             // x0-4 aligned to 16B
            float4 v0 = *(const float4*)(r0);
            float4 v1 = *(const float4*)(r0 + 4);
            float4 v2 = *(const float4*)(r0 + 8);
            const float nv[12] = {v0.x, v0.y, v0.z, v0.w,
                                  v1.x, v1.y, v1.z, v1.w,
                                  v2.x, v2.y, v2.z, v2.w};
            if (c < 3) {
                #pragma unroll
                for (int k = 0; k < 12; ++k) keep[c][k] = nv[k];
            }
            float nq[12];
            #pragma unroll
            for (int k = 1; k <= 10; ++k) nq[k] = nv[k] * nv[k];

            #pragma unroll
            for (int j = 0; j < 7; ++j) {
                #pragma unroll
                for (int p = 0; p < 4; ++p) {
                    const int t = j + p + 1;             // nv index for this tap
                    float tmp = fmaf(rp[c][p], nq[t], s[j][p]);
                    s[j][p]   = fmaf(mf[c][p], nv[t], tmp);
                }
            }
        }

        const float dy2 = (float)((i - 3) * (i - 3));
        float Kd[4];
        #pragma unroll
        for (int p = 0; p < 4; ++p) Kd[p] = fmaf(syl[p], dy2, K[p]);

        #pragma unroll
        for (int j = 0; j < 7; ++j) {
            const float dx2 = (float)((j - 3) * (j - 3));
            #pragma unroll
            for (int p = 0; p < 4; ++p) {
                const int t = j + p + 1;
                float lw = fmaf(sxl[p], dx2, s[j][p] + Kd[p]);
                float w  = __expf(lw);
                ws[p] += w;
                acc[0][p] = fmaf(w, keep[0][t], acc[0][p]);
                acc[1][p] = fmaf(w, keep[1][t], acc[1][p]);
                acc[2][p] = fmaf(w, keep[2][t], acc[2][p]);
            }
        }
    }

    float inv[4];
    #pragma unroll
    for (int p = 0; p < 4; ++p) inv[p] = 1.f / ws[p];

    float* ob = out + (long)b * 3 * HW + ctr;
    #pragma unroll
    for (int c = 0; c < 3; ++c) {
        float4 o;
        o.x = acc[c][0] * inv[0];
        o.y = acc[c][1] * inv[1];
        o.z = acc[c][2] * inv[2];
        o.w = acc[c][3] * inv[3];
        *(float4*)(ob + c * HW) = o;
    }
}

// ---------------------------------------------------------------------------
// Border kernel: the ring not covered by the interior kernel.
//   top:    y in [0,3)     full width          (3072 px)
//   bottom: y in [1021,1024) full width        (3072 px)
//   left:   x in [0,4),    y in [3,1021)       (4072 px)
//   right:  x in [1020,1024), y in [3,1021)    (4072 px)
// Total 14288 per batch. Direct (fn-f)^2 form with bounds checks.
// ---------------------------------------------------------------------------
__global__ void bilat_border(const float* __restrict__ in, float* __restrict__ out)
{
    constexpr int NB = 14288;
    int idx = blockIdx.x * blockDim.x + threadIdx.x;
    if (idx >= 2 * NB) return;
    const int b = idx / NB;
    int r = idx % NB;
    int x, y;
    if (r < 3072)        { y = r >> 10;                x = r & 1023; }
    else if (r < 6144)   { r -= 3072;  y = 1021 + (r >> 10); x = r & 1023; }
    else if (r < 10216)  { r -= 6144;  y = 3 + (r >> 2);     x = r & 3; }
    else                 { r -= 10216; y = 3 + (r >> 2);     x = 1020 + (r & 3); }

    const float* base = in + (long)b * CIN * HW;
    const long ctr = (long)y * Wd + x;

    float f[8], rp[8];
    #pragma unroll
    for (int c = 0; c < 8; ++c) {
        f[c] = base[c * HW + ctr];
        float pv = base[(8 + c) * HW + ctr];
        rp[c] = -(pv * pv);
    }
    float sv = base[16 * HW + ctr];
    float tv = base[17 * HW + ctr];
    const float sxl = -(sv * sv), syl = -(tv * tv);

    float a0 = 0.f, a1 = 0.f, a2 = 0.f, ws = 0.f;
    for (int i = 0; i < 7; ++i) {
        const int gy = y + i - 3;
        if (gy < 0 || gy >= Hd) continue;
        const float dy2 = (float)((i - 3) * (i - 3));
        for (int j = 0; j < 7; ++j) {
            const int gx = x + j - 3;
            if (gx < 0 || gx >= Wd) continue;
            const float dx2 = (float)((j - 3) * (j - 3));
            const float* q = base + (long)gy * Wd + gx;
            float fn[8];
            float lw = fmaf(sxl, dx2, syl * dy2);
            #pragma unroll
            for (int c = 0; c < 8; ++c) {
                fn[c] = q[c * HW];
                float d = fn[c] - f[c];
                lw = fmaf(rp[c], d * d, lw);
            }
            float w = __expf(lw);
            ws += w;
            a0 = fmaf(w, fn[0], a0);
            a1 = fmaf(w, fn[1], a1);
            a2 = fmaf(w, fn[2], a2);
        }
    }
    float* ob = out + (long)b * 3 * HW + ctr;
    const float inv = 1.f / ws;
    ob[0]      = a0 * inv;
    ob[HW]     = a1 * inv;
    ob[2 * HW] = a2 * inv;
}

extern "C" void kernel_launch(void* const* d_in, const int* in_sizes, int n_in,
                              void* d_out, int out_size)
{
    const float* in = (const float*)d_in[0];
    float* out = (float*)d_out;

    // Interior: 254 groups of 4px in x -> grid.x = 8 (32 lanes/block),
    // 1018 rows -> grid.y = 128 (8 rows/block), grid.z = batch.
    dim3 blk(32, 8, 1);
    dim3 grd(8, 128, 2);
    bilat_interior<<<grd, blk>>>(in, out);

    const int nb = (2 * 14288 + 255) / 256;
    bilat_border<<<nb, 256>>>(in, out);
}

// round 2
// speedup vs baseline: 1.0013x; 1.0013x over previous
#include <cuda_runtime.h>

constexpr int Wd = 1024, Hd = 1024;
constexpr long HW = (long)Wd * Hd;
constexpr int CIN = 18;
constexpr float L2E = 1.4426950408889634f;

using u64 = unsigned long long;

__device__ __forceinline__ u64 pack2(float lo, float hi) {
    u64 r; asm("mov.b64 %0,{%1,%2};" : "=l"(r) : "f"(lo), "f"(hi)); return r;
}
__device__ __forceinline__ void unpack2(u64 v, float& lo, float& hi) {
    asm("mov.b64 {%0,%1},%2;" : "=f"(lo), "=f"(hi) : "l"(v));
}
__device__ __forceinline__ u64 fma2(u64 a, u64 b, u64 c) {
    u64 d; asm("fma.rn.f32x2 %0,%1,%2,%3;" : "=l"(d) : "l"(a), "l"(b), "l"(c)); return d;
}
__device__ __forceinline__ u64 mul2(u64 a, u64 b) {
    u64 d; asm("mul.rn.f32x2 %0,%1,%2;" : "=l"(d) : "l"(a), "l"(b)); return d;
}
__device__ __forceinline__ u64 add2(u64 a, u64 b) {
    u64 d; asm("add.rn.f32x2 %0,%1,%2;" : "=l"(d) : "l"(a), "l"(b)); return d;
}
__device__ __forceinline__ float ex2(float x) {
    float r; asm("ex2.approx.f32 %0,%1;" : "=f"(r) : "f"(x)); return r;
}
// broadcast via pure integer ops -> constant-foldable for literals
__device__ __forceinline__ u64 bcast2(float x) {
    unsigned u = __float_as_uint(x); return ((u64)u << 32) | u;
}

// ---------------------------------------------------------------------------
// Interior: x in [4,1020), y in [3,1021). 4 px/thread, f32x2-packed math.
// All weight params pre-scaled by log2(e); per-tap weight via ex2.approx.
// ---------------------------------------------------------------------------
__device__ __forceinline__ void interior_path(const float* __restrict__ in,
                                              float* __restrict__ out,
                                              int bx, int byi, int bz)
{
    const int gxg = bx * 32 + threadIdx.x;
    const int x0  = 4 + gxg * 4;
    const int y   = 3 + byi * 8 + threadIdx.y;
    if (x0 > 1016 || y > 1020) return;

    const float* base = in + (long)bz * CIN * HW;
    const long ctr = (long)y * Wd + x0;

    u64 rp2[8][2], mf2[8][2], K2[2], sxl2[2], syl2[2];
    {
        float Ks[4] = {0.f, 0.f, 0.f, 0.f};
        #pragma unroll
        for (int c = 0; c < 8; ++c) {
            float4 fv = *(const float4*)(base + c * HW + ctr);
            float4 pv = *(const float4*)(base + (8 + c) * HW + ctr);
            const float f4[4] = {fv.x, fv.y, fv.z, fv.w};
            const float p4[4] = {pv.x, pv.y, pv.z, pv.w};
            float rs[4], ms[4];
            #pragma unroll
            for (int p = 0; p < 4; ++p) {
                float r = -(p4[p] * p4[p]) * L2E;       // L2E folded in
                rs[p] = r;
                ms[p] = -2.f * r * f4[p];
                Ks[p] = fmaf(r * f4[p], f4[p], Ks[p]);
            }
            rp2[c][0] = pack2(rs[0], rs[1]); rp2[c][1] = pack2(rs[2], rs[3]);
            mf2[c][0] = pack2(ms[0], ms[1]); mf2[c][1] = pack2(ms[2], ms[3]);
        }
        K2[0] = pack2(Ks[0], Ks[1]); K2[1] = pack2(Ks[2], Ks[3]);
        float4 sv = *(const float4*)(base + 16 * HW + ctr);
        float4 tv = *(const float4*)(base + 17 * HW + ctr);
        sxl2[0] = pack2(-(sv.x*sv.x)*L2E, -(sv.y*sv.y)*L2E);
        sxl2[1] = pack2(-(sv.z*sv.z)*L2E, -(sv.w*sv.w)*L2E);
        syl2[0] = pack2(-(tv.x*tv.x)*L2E, -(tv.y*tv.y)*L2E);
        syl2[1] = pack2(-(tv.z*tv.z)*L2E, -(tv.w*tv.w)*L2E);
    }

    u64 acc2[3][2] = {}, ws2[2] = {};

    #pragma unroll 1        // ~9KB body: stays inside I$ L1.5
    for (int i = 0; i < 7; ++i) {
        const int gy = y + i - 3;                       // always in [0,1023]
        const float* rowb = base + (long)gy * Wd + (x0 - 4);
        const float dy2 = (float)((i - 3) * (i - 3));
        const u64 dyb = bcast2(dy2);

        // s2 initialized to Kd = syl*dy2 + K (moves the epilogue add off fma pipe)
        u64 s2[7][2];
        {
            const u64 kd0 = fma2(syl2[0], dyb, K2[0]);
            const u64 kd1 = fma2(syl2[1], dyb, K2[1]);
            #pragma unroll
            for (int j = 0; j < 7; ++j) { s2[j][0] = kd0; s2[j][1] = kd1; }
        }

        #pragma unroll
        for (int c = 0; c < 8; ++c) {
            const float* r0 = rowb + c * HW;            // 16B aligned
            float4 v0 = *(const float4*)(r0);
            float4 v1 = *(const float4*)(r0 + 4);
            float4 v2 = *(const float4*)(r0 + 8);
            const float nv[12] = {v0.x, v0.y, v0.z, v0.w,
                                  v1.x, v1.y, v1.z, v1.w,
                                  v2.x, v2.y, v2.z, v2.w};
            u64 pv[9], pq[9];
            #pragma unroll
            for (int k = 0; k < 9; ++k) {
                pv[k] = pack2(nv[k + 1], nv[k + 2]);
                pq[k] = mul2(pv[k], pv[k]);
            }
            #pragma unroll
            for (int j = 0; j < 7; ++j) {
                s2[j][0] = fma2(mf2[c][0], pv[j],     fma2(rp2[c][0], pq[j],     s2[j][0]));
                s2[j][1] = fma2(mf2[c][1], pv[j + 2], fma2(rp2[c][1], pq[j + 2], s2[j][1]));
            }
        }

        // Reload the 3 output-channel rows (L1-hit) instead of keeping them live
        u64 kp[3][9];
        #pragma unroll
        for (int c = 0; c < 3; ++c) {
            const float* r0 = rowb + c * HW;
            float4 v0 = *(const float4*)(r0);
            float4 v1 = *(const float4*)(r0 + 4);
            float4 v2 = *(const float4*)(r0 + 8);
            const float nv[12] = {v0.x, v0.y, v0.z, v0.w,
                                  v1.x, v1.y, v1.z, v1.w,
                                  v2.x, v2.y, v2.z, v2.w};
            #pragma unroll
            for (int k = 0; k < 9; ++k) kp[c][k] = pack2(nv[k + 1], nv[k + 2]);
        }

        #pragma unroll
        for (int j = 0; j < 7; ++j) {
            const float dx2 = (float)((j - 3) * (j - 3));
            const u64 dxb = bcast2(dx2);
            #pragma unroll
            for (int pp = 0; pp < 2; ++pp) {
                u64 lw2 = fma2(sxl2[pp], dxb, s2[j][pp]);
                float a, b; unpack2(lw2, a, b);
                u64 w2 = pack2(ex2(a), ex2(b));
                ws2[pp] = add2(ws2[pp], w2);
                const int t = j + 2 * pp;
                acc2[0][pp] = fma2(w2, kp[0][t], acc2[0][pp]);
                acc2[1][pp] = fma2(w2, kp[1][t], acc2[1][pp]);
                acc2[2][pp] = fma2(w2, kp[2][t], acc2[2][pp]);
            }
        }
    }

    float ws[4];
    unpack2(ws2[0], ws[0], ws[1]); unpack2(ws2[1], ws[2], ws[3]);
    float inv[4];
    #pragma unroll
    for (int p = 0; p < 4; ++p) inv[p] = 1.f / ws[p];

    float* ob = out + (long)bz * 3 * HW + ctr;
    #pragma unroll
    for (int c = 0; c < 3; ++c) {
        float a0, a1, a2, a3;
        unpack2(acc2[c][0], a0, a1); unpack2(acc2[c][1], a2, a3);
        float4 o; o.x = a0 * inv[0]; o.y = a1 * inv[1]; o.z = a2 * inv[2]; o.w = a3 * inv[3];
        *(float4*)(ob + c * HW) = o;
    }
}

// ---------------------------------------------------------------------------
// Border ring: 14288 px/batch, direct form with bounds checks. Latency-bound;
// runs concurrently under the interior (its blocks launch first).
// ---------------------------------------------------------------------------
__device__ __forceinline__ void border_path(const float* __restrict__ in,
                                            float* __restrict__ out,
                                            int bid, int bz)
{
    const int tid = threadIdx.y * 32 + threadIdx.x;
    int r = bid * 256 + tid;
    if (r >= 14288) return;
    int x, y;
    if (r < 3072)        { y = r >> 10;                x = r & 1023; }
    else if (r < 6144)   { r -= 3072;  y = 1021 + (r >> 10); x = r & 1023; }
    else if (r < 10216)  { r -= 6144;  y = 3 + (r >> 2);     x = r & 3; }
    else                 { r -= 10216; y = 3 + (r >> 2);     x = 1020 + (r & 3); }

    const float* base = in + (long)bz * CIN * HW;
    const long ctr = (long)y * Wd + x;

    float f[8], rp[8];
    #pragma unroll
    for (int c = 0; c < 8; ++c) {
        f[c] = base[c * HW + ctr];
        float pv = base[(8 + c) * HW + ctr];
        rp[c] = -(pv * pv);
    }
    float sv = base[16 * HW + ctr];
    float tv = base[17 * HW + ctr];
    const float sxl = -(sv * sv), syl = -(tv * tv);

    float a0 = 0.f, a1 = 0.f, a2 = 0.f, ws = 0.f;
    for (int i = 0; i < 7; ++i) {
        const int gy = y + i - 3;
        if (gy < 0 || gy >= Hd) continue;
        const float dy2 = (float)((i - 3) * (i - 3));
        for (int j = 0; j < 7; ++j) {
            const int gx = x + j - 3;
            if (gx < 0 || gx >= Wd) continue;
            const float dx2 = (float)((j - 3) * (j - 3));
            const float* q = base + (long)gy * Wd + gx;
            float fn[8];
            float lw = fmaf(sxl, dx2, syl * dy2);
            #pragma unroll
            for (int c = 0; c < 8; ++c) {
                fn[c] = q[c * HW];
                float d = fn[c] - f[c];
                lw = fmaf(rp[c], d * d, lw);
            }
            float w = __expf(lw);
            ws += w;
            a0 = fmaf(w, fn[0], a0);
            a1 = fmaf(w, fn[1], a1);
            a2 = fmaf(w, fn[2], a2);
        }
    }
    float* ob = out + (long)bz * 3 * HW + ctr;
    const float inv = 1.f / ws;
    ob[0]      = a0 * inv;
    ob[HW]     = a1 * inv;
    ob[2 * HW] = a2 * inv;
}

// Single fused kernel. Border blocks occupy blockIdx.y in [0,7) so they are
// enumerated (and scheduled) FIRST and hide under the interior wave.
__global__ __launch_bounds__(256, 1)
void bilat_fused(const float* __restrict__ in, float* __restrict__ out)
{
    if (blockIdx.y < 7) {
        border_path(in, out, blockIdx.y * 8 + blockIdx.x, blockIdx.z);
    } else {
        interior_path(in, out, blockIdx.x, blockIdx.y - 7, blockIdx.z);
    }
}

extern "C" void kernel_launch(void* const* d_in, const int* in_sizes, int n_in,
                              void* d_out, int out_size)
{
    const float* in = (const float*)d_in[0];
    float* out = (float*)d_out;

    dim3 blk(32, 8, 1);
    dim3 grd(8, 135, 2);   // y: 7 border block-rows + 128 interior block-rows
    bilat_fused<<<grd, blk>>>(in, out);
}